// round 11
// baseline (speedup 1.0000x reference)
#include <cuda_runtime.h>

#define HH 256
#define WW 256
#define NW 8                 // 256 cols / 32
#define NPIX (8 * HH * WW)   // mean denominator
#define NBLK 1024            // 128 bands x 8 batch
#define BAND 2               // core rows per block
#define WROWS 8              // window rows = BAND + 2*3

__device__ float    g_accum = 0.0f;
__device__ unsigned g_done  = 0u;

// ---------------------------------------------------------------------------
// Exact fallback: expanding float-based scan for nearest opposite-class pixel.
// Reached only when no opposite pixel lies within r^2 <= 13 (prob ~1e-4 of
// ANY event in this input). Exact for all inputs; 1e20 if none exists.
// ---------------------------------------------------------------------------
__device__ __noinline__ float slow_scan(const float* __restrict__ im, int i, int j, bool cls) {
    float best = 1e20f;
    for (int dd = 0; dd < HH; ++dd) {
        float dd2 = (float)(dd * dd);
        if (dd2 >= best) break;
#pragma unroll 1
        for (int s2 = 0; s2 < 2; ++s2) {
            if (s2 && dd == 0) continue;
            int r = s2 ? i - dd : i + dd;
            if (r < 0 || r >= HH) continue;
            const float* row = im + (size_t)r * WW;
            for (int dj = 0; dj < WW; ++dj) {
                float tot = dd2 + (float)(dj * dj);
                if (tot >= best) break;
                int c1 = j + dj, c2 = j - dj;
                if (c1 < WW && ((row[c1] > 0.5f) != cls)) { best = tot; break; }
                if (dj && c2 >= 0 && ((row[c2] > 0.5f) != cls)) { best = tot; break; }
            }
        }
    }
    return best;
}

// ---------------------------------------------------------------------------
// Single fused kernel, BAND=2 for 2x grid parallelism (1024 blocks).
// Block = (band of 2 rows, batch), 256 threads (8 warps).
// Phase 0: warp = window row (8 rows); 16 front-batched LDGs/thread; ballots
//          build masks; warps 3,4 stage w = (p-t)^2.
// Phase 1: warp 0, lane = (image, row, word) task -> 4 bit-planes, gated
//          levels r^2 in {1,2,4,5,8} + {9,10,13}. s = p0+2p1+4p2+8p3.
// Phase 2: warp = (row, quarter), 2 words each: acc += w*(s_pred+s_target);
//          s==0 -> exact slow_scan.
// Output: last-block finalize (idempotent across graph replays).
// ---------------------------------------------------------------------------
__global__ void __launch_bounds__(256) hd_loss_kernel(const float* __restrict__ pred,
                                                      const float* __restrict__ target,
                                                      float* __restrict__ out) {
    int band = blockIdx.x;          // 0..127
    int b    = blockIdx.y;          // 0..7
    int tid  = threadIdx.x;         // 0..255
    int lane = tid & 31;
    int warp = tid >> 5;            // 0..7

    __shared__ unsigned SM[2][WROWS][10];   // window rows band*2-3..+4, pad cols 0,9
    __shared__ uint4    SP[2][BAND][NW];    // bit-planes p0..p3
    __shared__ float    w_sh[BAND][WW];     // (p-t)^2 core rows
    __shared__ float    sred[8];

    const float* pbase = pred   + (size_t)b * HH * WW;
    const float* tbase = target + (size_t)b * HH * WW;

    // zero pads: 2 img x 8 rows x 2 pad cols = 32 slots
    if (tid < 32) {
        int f = tid >> 4, rr = (tid >> 1) & 7, cc = tid & 1;
        SM[f][rr][cc * 9] = 0u;
    }

    // ---------------- Phase 0: warp = window row; 16 batched LDGs ----------------
    {
        int gi = band * BAND - 3 + warp;
        gi = gi < 0 ? 0 : (gi > HH - 1 ? HH - 1 : gi);   // clamp; rv masks fix validity
        const float* pr = pbase + (size_t)gi * WW + lane;
        const float* tr = tbase + (size_t)gi * WW + lane;
        float vp[NW], vt[NW];
#pragma unroll
        for (int k = 0; k < NW; ++k) {      // 16 independent LDGs
            vp[k] = pr[k * 32];
            vt[k] = tr[k * 32];
        }
#pragma unroll
        for (int k = 0; k < NW; ++k) {
            unsigned mp = __ballot_sync(0xFFFFFFFFu, vp[k] > 0.5f);
            unsigned mt = __ballot_sync(0xFFFFFFFFu, vt[k] > 0.5f);
            if (lane == 0) {
                SM[0][warp][k + 1] = mp;
                SM[1][warp][k + 1] = mt;
            }
        }
        if (warp == 3 || warp == 4) {
            int core = warp - 3;
#pragma unroll
            for (int k = 0; k < NW; ++k) {
                float d = vp[k] - vt[k];
                w_sh[core][k * 32 + lane] = d * d;
            }
        }
    }
    __syncthreads();

    // ---------------- Phase 1: warp 0, lane = task (32 tasks) ----------------
    if (tid < 32) {
        int f1 = lane >> 4;         // 0 = pred, 1 = target
        int rr = (lane >> 3) & 1;   // core row in band
        int w1 = lane & 7;          // word
        int i1 = band * BAND + rr;
        int sr = rr + 3;
        const unsigned (*M)[10] = SM[f1];

        unsigned W   = M[sr][w1 + 1];
        unsigned l0  = M[sr][w1],         r0  = M[sr][w1 + 2];
        unsigned cU1 = M[sr - 1][w1 + 1], lU1 = M[sr - 1][w1], rU1 = M[sr - 1][w1 + 2];
        unsigned cD1 = M[sr + 1][w1 + 1], lD1 = M[sr + 1][w1], rD1 = M[sr + 1][w1 + 2];

        unsigned mlo1 = (w1 == 0) ? 0xFFFFFFFEu : 0xFFFFFFFFu;
        unsigned mlo2 = (w1 == 0) ? 0xFFFFFFFCu : 0xFFFFFFFFu;
        unsigned mlo3 = (w1 == 0) ? 0xFFFFFFF8u : 0xFFFFFFFFu;
        unsigned mhi1 = (w1 == 7) ? 0x7FFFFFFFu : 0xFFFFFFFFu;
        unsigned mhi2 = (w1 == 7) ? 0x3FFFFFFFu : 0xFFFFFFFFu;
        unsigned mhi3 = (w1 == 7) ? 0x1FFFFFFFu : 0xFFFFFFFFu;
        unsigned rvU1 = (i1 >= 1)      ? 0xFFFFFFFFu : 0u;
        unsigned rvD1 = (i1 <= HH - 2) ? 0xFFFFFFFFu : 0u;
        unsigned rvU2 = (i1 >= 2)      ? 0xFFFFFFFFu : 0u;
        unsigned rvD2 = (i1 <= HH - 3) ? 0xFFFFFFFFu : 0u;
        unsigned rvU3 = (i1 >= 3)      ? 0xFFFFFFFFu : 0u;
        unsigned rvD3 = (i1 <= HH - 4) ? 0xFFFFFFFFu : 0u;

        // s=1: (0,+-1), (+-1,0)
        unsigned h1 = ((W ^ __funnelshift_l(l0, W, 1)) & mlo1)
                    | ((W ^ __funnelshift_r(W, r0, 1)) & mhi1)
                    | ((W ^ cU1) & rvU1) | ((W ^ cD1) & rvD1);
        // s=2: (+-1,+-1)
        unsigned h2 = (((((W ^ __funnelshift_l(lU1, cU1, 1)) & mlo1)
                       | ((W ^ __funnelshift_r(cU1, rU1, 1)) & mhi1)) & rvU1)
                     | ((((W ^ __funnelshift_l(lD1, cD1, 1)) & mlo1)
                       | ((W ^ __funnelshift_r(cD1, rD1, 1)) & mhi1)) & rvD1)) & ~h1;
        unsigned p0 = h1, p1 = h2, p2 = 0u, p3 = 0u;
        unsigned U = ~(h1 | h2);
        if (U) {
            unsigned cU2 = M[sr - 2][w1 + 1], lU2 = M[sr - 2][w1], rU2 = M[sr - 2][w1 + 2];
            unsigned cD2 = M[sr + 2][w1 + 1], lD2 = M[sr + 2][w1], rD2 = M[sr + 2][w1 + 2];
            // s=4: (0,+-2), (+-2,0)
            unsigned h4 = (((W ^ __funnelshift_l(l0, W, 2)) & mlo2)
                         | ((W ^ __funnelshift_r(W, r0, 2)) & mhi2)
                         | ((W ^ cU2) & rvU2) | ((W ^ cD2) & rvD2)) & U;
            p2 = h4; U &= ~h4;
            // s=5: (+-1,+-2), (+-2,+-1)
            unsigned h5 = (((((W ^ __funnelshift_l(lU1, cU1, 2)) & mlo2)
                           | ((W ^ __funnelshift_r(cU1, rU1, 2)) & mhi2)) & rvU1)
                         | ((((W ^ __funnelshift_l(lD1, cD1, 2)) & mlo2)
                           | ((W ^ __funnelshift_r(cD1, rD1, 2)) & mhi2)) & rvD1)
                         | ((((W ^ __funnelshift_l(lU2, cU2, 1)) & mlo1)
                           | ((W ^ __funnelshift_r(cU2, rU2, 1)) & mhi1)) & rvU2)
                         | ((((W ^ __funnelshift_l(lD2, cD2, 1)) & mlo1)
                           | ((W ^ __funnelshift_r(cD2, rD2, 1)) & mhi1)) & rvD2)) & U;
            p0 |= h5; p2 |= h5; U &= ~h5;
            // s=8: (+-2,+-2)
            unsigned h8 = (((((W ^ __funnelshift_l(lU2, cU2, 2)) & mlo2)
                           | ((W ^ __funnelshift_r(cU2, rU2, 2)) & mhi2)) & rvU2)
                         | ((((W ^ __funnelshift_l(lD2, cD2, 2)) & mlo2)
                           | ((W ^ __funnelshift_r(cD2, rD2, 2)) & mhi2)) & rvD2)) & U;
            p3 = h8; U &= ~h8;
            if (U) {  // essentially only border words
                unsigned cU3 = M[sr - 3][w1 + 1], lU3 = M[sr - 3][w1], rU3 = M[sr - 3][w1 + 2];
                unsigned cD3 = M[sr + 3][w1 + 1], lD3 = M[sr + 3][w1], rD3 = M[sr + 3][w1 + 2];
                // s=9: (0,+-3), (+-3,0)
                unsigned h9 = (((W ^ __funnelshift_l(l0, W, 3)) & mlo3)
                             | ((W ^ __funnelshift_r(W, r0, 3)) & mhi3)
                             | ((W ^ cU3) & rvU3) | ((W ^ cD3) & rvD3)) & U;
                p0 |= h9; p3 |= h9; U &= ~h9;
                // s=10: (+-1,+-3), (+-3,+-1)
                unsigned h10 = (((((W ^ __funnelshift_l(lU1, cU1, 3)) & mlo3)
                                | ((W ^ __funnelshift_r(cU1, rU1, 3)) & mhi3)) & rvU1)
                              | ((((W ^ __funnelshift_l(lD1, cD1, 3)) & mlo3)
                                | ((W ^ __funnelshift_r(cD1, rD1, 3)) & mhi3)) & rvD1)
                              | ((((W ^ __funnelshift_l(lU3, cU3, 1)) & mlo1)
                                | ((W ^ __funnelshift_r(cU3, rU3, 1)) & mhi1)) & rvU3)
                              | ((((W ^ __funnelshift_l(lD3, cD3, 1)) & mlo1)
                                | ((W ^ __funnelshift_r(cD3, rD3, 1)) & mhi1)) & rvD3)) & U;
                p1 |= h10; p3 |= h10; U &= ~h10;
                // s=13: (+-2,+-3), (+-3,+-2)
                unsigned h13 = (((((W ^ __funnelshift_l(lU2, cU2, 3)) & mlo3)
                                | ((W ^ __funnelshift_r(cU2, rU2, 3)) & mhi3)) & rvU2)
                              | ((((W ^ __funnelshift_l(lD2, cD2, 3)) & mlo3)
                                | ((W ^ __funnelshift_r(cD2, rD2, 3)) & mhi3)) & rvD2)
                              | ((((W ^ __funnelshift_l(lU3, cU3, 2)) & mlo2)
                                | ((W ^ __funnelshift_r(cU3, rU3, 2)) & mhi2)) & rvU3)
                              | ((((W ^ __funnelshift_l(lD3, cD3, 2)) & mlo2)
                                | ((W ^ __funnelshift_r(cD3, rD3, 2)) & mhi2)) & rvD3)) & U;
                p0 |= h13; p2 |= h13; p3 |= h13;
                // unresolved keeps all-planes-0 -> exact fallback
            }
        }
        SP[f1][rr][w1] = make_uint4(p0, p1, p2, p3);
    }
    __syncthreads();

    // ---------------- Phase 2: warp = (row, quarter), lane = pixel ----------------
    int row  = warp >> 2;           // 0..1
    int quar = warp & 3;            // 2-word group
    int i2   = band * BAND + row;
    float acc = 0.0f;
    unsigned fb = 0u;               // fallback events: bit = wq*2 + side
#pragma unroll
    for (int wq = 0; wq < 2; ++wq) {
        int ww = quar * 2 + wq;
        float w = w_sh[row][ww * 32 + lane];
        uint4 P = SP[0][row][ww];
        uint4 Q = SP[1][row][ww];
        int sp = (int)((P.x >> lane) & 1u) | ((int)((P.y >> lane) & 1u) << 1)
               | ((int)((P.z >> lane) & 1u) << 2) | ((int)((P.w >> lane) & 1u) << 3);
        int st = (int)((Q.x >> lane) & 1u) | ((int)((Q.y >> lane) & 1u) << 1)
               | ((int)((Q.z >> lane) & 1u) << 2) | ((int)((Q.w >> lane) & 1u) << 3);
        fb |= (sp == 0 ? 1u : 0u) << (wq * 2);
        fb |= (st == 0 ? 2u : 0u) << (wq * 2);
        acc += w * (float)(sp + st);
    }
    // exact fallback (prob ~1e-4 of ANY event in this input)
    while (fb) {
        int e = __ffs(fb) - 1; fb &= fb - 1;
        int side = e & 1, wq = e >> 1;
        int col = (quar * 2 + wq) * 32 + lane;
        const float* ib = side ? tbase : pbase;
        bool cls = ib[(size_t)i2 * WW + col] > 0.5f;
        acc += w_sh[row][col] * slow_scan(ib, i2, col, cls);
    }

    // reduce: warp -> block
#pragma unroll
    for (int o = 16; o > 0; o >>= 1) acc += __shfl_xor_sync(0xFFFFFFFFu, acc, o);
    if (lane == 0) sred[warp] = acc;
    __syncthreads();

    // block partial -> global accumulator; last block finalizes + resets
    if (tid == 0) {
        float sum = 0.0f;
#pragma unroll
        for (int k = 0; k < 8; ++k) sum += sred[k];
        atomicAdd(&g_accum, sum);
        __threadfence();
        unsigned prev = atomicAdd(&g_done, 1u);
        if (prev == NBLK - 1) {
            float tot = *(volatile float*)&g_accum;
            *out = tot * (1.0f / (float)NPIX);
            *(volatile float*)&g_accum = 0.0f;      // reset for next graph replay
            *(volatile unsigned*)&g_done = 0u;
            __threadfence();
        }
    }
}

extern "C" void kernel_launch(void* const* d_in, const int* in_sizes, int n_in,
                              void* d_out, int out_size) {
    const float* pred   = (const float*)d_in[0];
    const float* target = (const float*)d_in[1];
    float* out = (float*)d_out;

    hd_loss_kernel<<<dim3(128, 8), 256>>>(pred, target, out);
}

// round 12
// speedup vs baseline: 1.1283x; 1.1283x over previous
#include <cuda_runtime.h>

#define HH 256
#define WW 256
#define NW 8                 // 256 cols / 32
#define NPIX (8 * HH * WW)   // mean denominator
#define NBLK 512             // 64 bands x 8 batch
#define BAND 4               // core rows per block
#define WROWS 10             // window rows = BAND + 2*3

__device__ float    g_accum = 0.0f;
__device__ unsigned g_done  = 0u;

// ---------------------------------------------------------------------------
// Exact fallback: expanding float-based scan for nearest opposite-class pixel.
// Reached only when no opposite pixel lies within r^2 <= 13 (prob ~1e-4 of
// ANY event in this input). Exact for all inputs; 1e20 if none exists.
// ---------------------------------------------------------------------------
__device__ __noinline__ float slow_scan(const float* __restrict__ im, int i, int j, bool cls) {
    float best = 1e20f;
    for (int dd = 0; dd < HH; ++dd) {
        float dd2 = (float)(dd * dd);
        if (dd2 >= best) break;
#pragma unroll 1
        for (int s2 = 0; s2 < 2; ++s2) {
            if (s2 && dd == 0) continue;
            int r = s2 ? i - dd : i + dd;
            if (r < 0 || r >= HH) continue;
            const float* row = im + (size_t)r * WW;
            for (int dj = 0; dj < WW; ++dj) {
                float tot = dd2 + (float)(dj * dj);
                if (tot >= best) break;
                int c1 = j + dj, c2 = j - dj;
                if (c1 < WW && ((row[c1] > 0.5f) != cls)) { best = tot; break; }
                if (dj && c2 >= 0 && ((row[c2] > 0.5f) != cls)) { best = tot; break; }
            }
        }
    }
    return best;
}

// ---------------------------------------------------------------------------
// Single fused kernel (R8 structure; phase 0 via float4 + shfl assembly).
// Block = (band of 4 rows, batch), 256 threads (8 warps).
// Phase 0: task = window row; thread loads 8 cols of BOTH images (4 LDG.128),
//          builds byte masks, 3-shfl tree assembles both 32-bit words; stages
//          w = (p-t)^2 via STS.128.
// Phase 1: threads 0..63 = (image, row, word) -> 4 bit-planes, gated levels
//          r^2 in {1,2,4,5,8} + {9,10,13}. s = p0+2p1+4p2+8p3.
// Phase 2: warp = (row, word-half), lane = pixel: acc += w*(s_pred+s_target);
//          s==0 -> exact slow_scan.
// Output: last-block finalize (idempotent across graph replays).
// ---------------------------------------------------------------------------
__global__ void __launch_bounds__(256) hd_loss_kernel(const float* __restrict__ pred,
                                                      const float* __restrict__ target,
                                                      float* __restrict__ out) {
    int band = blockIdx.x;          // 0..63
    int b    = blockIdx.y;          // 0..7
    int tid  = threadIdx.x;         // 0..255
    int lane = tid & 31;
    int warp = tid >> 5;            // 0..7

    __shared__ unsigned SM[2][WROWS][10];            // window rows, pad cols 0,9
    __shared__ uint4    SP[2][BAND][NW];             // bit-planes p0..p3
    __shared__ __align__(16) float w_sh[BAND][WW];   // (p-t)^2 core rows
    __shared__ float    sred[8];

    const float* pbase = pred   + (size_t)b * HH * WW;
    const float* tbase = target + (size_t)b * HH * WW;

    // zero pads: 2 img x 10 rows x 2 pad cols = 40 slots
    if (tid < 40) {
        int f = tid / 20, rr = (tid >> 1) % 10, cc = tid & 1;
        SM[f][rr][cc * 9] = 0u;
    }

    // ---------------- Phase 0: float4 loads + shfl word assembly ----------------
    // task = window row (10); thread covers cols 8*lane..8*lane+7 of both images.
#pragma unroll
    for (int T = warp; T < WROWS; T += 8) {
        int gi = band * BAND - 3 + T;
        gi = gi < 0 ? 0 : (gi > HH - 1 ? HH - 1 : gi);   // clamp; rv masks fix validity
        const float4* prow = (const float4*)(pbase + (size_t)gi * WW);
        const float4* trow = (const float4*)(tbase + (size_t)gi * WW);
        float4 pa = prow[2 * lane], pb = prow[2 * lane + 1];
        float4 ta = trow[2 * lane], tb = trow[2 * lane + 1];

        unsigned bp = (pa.x > 0.5f ? 1u : 0u) | (pa.y > 0.5f ? 2u : 0u)
                    | (pa.z > 0.5f ? 4u : 0u) | (pa.w > 0.5f ? 8u : 0u)
                    | (pb.x > 0.5f ? 16u : 0u) | (pb.y > 0.5f ? 32u : 0u)
                    | (pb.z > 0.5f ? 64u : 0u) | (pb.w > 0.5f ? 128u : 0u);
        unsigned bt = (ta.x > 0.5f ? 1u : 0u) | (ta.y > 0.5f ? 2u : 0u)
                    | (ta.z > 0.5f ? 4u : 0u) | (ta.w > 0.5f ? 8u : 0u)
                    | (tb.x > 0.5f ? 16u : 0u) | (tb.y > 0.5f ? 32u : 0u)
                    | (tb.z > 0.5f ? 64u : 0u) | (tb.w > 0.5f ? 128u : 0u);

        // carrier: pred byte in bits 0..7, target byte in bits 16..23
        unsigned u = bp | (bt << 16);
        u |= __shfl_down_sync(0xFFFFFFFFu, u, 1) << 8;   // 16 valid bits per half (even lanes)
        unsigned lo = u & 0xFFFFu;
        unsigned hi = u >> 16;
        lo |= __shfl_down_sync(0xFFFFFFFFu, lo, 2) << 16;
        hi |= __shfl_down_sync(0xFFFFFFFFu, hi, 2) << 16;
        if ((lane & 3) == 0) {                            // 8 groups = 8 words
            int wd = lane >> 2;
            SM[0][T][wd + 1] = lo;
            SM[1][T][wd + 1] = hi;
        }

        if (T >= 3 && T < 3 + BAND) {                     // core row: stage w
            float4 d0, d1;
            d0.x = pa.x - ta.x; d0.y = pa.y - ta.y; d0.z = pa.z - ta.z; d0.w = pa.w - ta.w;
            d1.x = pb.x - tb.x; d1.y = pb.y - tb.y; d1.z = pb.z - tb.z; d1.w = pb.w - tb.w;
            d0.x *= d0.x; d0.y *= d0.y; d0.z *= d0.z; d0.w *= d0.w;
            d1.x *= d1.x; d1.y *= d1.y; d1.z *= d1.z; d1.w *= d1.w;
            float4* wrow = (float4*)&w_sh[T - 3][0];
            wrow[2 * lane]     = d0;
            wrow[2 * lane + 1] = d1;
        }
    }
    __syncthreads();

    // ---------------- Phase 1: one word-task per thread (64 tasks) ----------------
    if (tid < 64) {
        int f1 = tid >> 5;          // 0 = pred, 1 = target
        int rr = (tid >> 3) & 3;    // core row in band
        int w1 = tid & 7;           // word
        int i1 = band * BAND + rr;
        int sr = rr + 3;
        const unsigned (*M)[10] = SM[f1];

        unsigned W   = M[sr][w1 + 1];
        unsigned l0  = M[sr][w1],         r0  = M[sr][w1 + 2];
        unsigned cU1 = M[sr - 1][w1 + 1], lU1 = M[sr - 1][w1], rU1 = M[sr - 1][w1 + 2];
        unsigned cD1 = M[sr + 1][w1 + 1], lD1 = M[sr + 1][w1], rD1 = M[sr + 1][w1 + 2];

        unsigned mlo1 = (w1 == 0) ? 0xFFFFFFFEu : 0xFFFFFFFFu;
        unsigned mlo2 = (w1 == 0) ? 0xFFFFFFFCu : 0xFFFFFFFFu;
        unsigned mlo3 = (w1 == 0) ? 0xFFFFFFF8u : 0xFFFFFFFFu;
        unsigned mhi1 = (w1 == 7) ? 0x7FFFFFFFu : 0xFFFFFFFFu;
        unsigned mhi2 = (w1 == 7) ? 0x3FFFFFFFu : 0xFFFFFFFFu;
        unsigned mhi3 = (w1 == 7) ? 0x1FFFFFFFu : 0xFFFFFFFFu;
        unsigned rvU1 = (i1 >= 1)      ? 0xFFFFFFFFu : 0u;
        unsigned rvD1 = (i1 <= HH - 2) ? 0xFFFFFFFFu : 0u;
        unsigned rvU2 = (i1 >= 2)      ? 0xFFFFFFFFu : 0u;
        unsigned rvD2 = (i1 <= HH - 3) ? 0xFFFFFFFFu : 0u;
        unsigned rvU3 = (i1 >= 3)      ? 0xFFFFFFFFu : 0u;
        unsigned rvD3 = (i1 <= HH - 4) ? 0xFFFFFFFFu : 0u;

        // s=1: (0,+-1), (+-1,0)
        unsigned h1 = ((W ^ __funnelshift_l(l0, W, 1)) & mlo1)
                    | ((W ^ __funnelshift_r(W, r0, 1)) & mhi1)
                    | ((W ^ cU1) & rvU1) | ((W ^ cD1) & rvD1);
        // s=2: (+-1,+-1)
        unsigned h2 = (((((W ^ __funnelshift_l(lU1, cU1, 1)) & mlo1)
                       | ((W ^ __funnelshift_r(cU1, rU1, 1)) & mhi1)) & rvU1)
                     | ((((W ^ __funnelshift_l(lD1, cD1, 1)) & mlo1)
                       | ((W ^ __funnelshift_r(cD1, rD1, 1)) & mhi1)) & rvD1)) & ~h1;
        unsigned p0 = h1, p1 = h2, p2 = 0u, p3 = 0u;
        unsigned U = ~(h1 | h2);
        if (U) {
            unsigned cU2 = M[sr - 2][w1 + 1], lU2 = M[sr - 2][w1], rU2 = M[sr - 2][w1 + 2];
            unsigned cD2 = M[sr + 2][w1 + 1], lD2 = M[sr + 2][w1], rD2 = M[sr + 2][w1 + 2];
            // s=4: (0,+-2), (+-2,0)
            unsigned h4 = (((W ^ __funnelshift_l(l0, W, 2)) & mlo2)
                         | ((W ^ __funnelshift_r(W, r0, 2)) & mhi2)
                         | ((W ^ cU2) & rvU2) | ((W ^ cD2) & rvD2)) & U;
            p2 = h4; U &= ~h4;
            // s=5: (+-1,+-2), (+-2,+-1)
            unsigned h5 = (((((W ^ __funnelshift_l(lU1, cU1, 2)) & mlo2)
                           | ((W ^ __funnelshift_r(cU1, rU1, 2)) & mhi2)) & rvU1)
                         | ((((W ^ __funnelshift_l(lD1, cD1, 2)) & mlo2)
                           | ((W ^ __funnelshift_r(cD1, rD1, 2)) & mhi2)) & rvD1)
                         | ((((W ^ __funnelshift_l(lU2, cU2, 1)) & mlo1)
                           | ((W ^ __funnelshift_r(cU2, rU2, 1)) & mhi1)) & rvU2)
                         | ((((W ^ __funnelshift_l(lD2, cD2, 1)) & mlo1)
                           | ((W ^ __funnelshift_r(cD2, rD2, 1)) & mhi1)) & rvD2)) & U;
            p0 |= h5; p2 |= h5; U &= ~h5;
            // s=8: (+-2,+-2)
            unsigned h8 = (((((W ^ __funnelshift_l(lU2, cU2, 2)) & mlo2)
                           | ((W ^ __funnelshift_r(cU2, rU2, 2)) & mhi2)) & rvU2)
                         | ((((W ^ __funnelshift_l(lD2, cD2, 2)) & mlo2)
                           | ((W ^ __funnelshift_r(cD2, rD2, 2)) & mhi2)) & rvD2)) & U;
            p3 = h8; U &= ~h8;
            if (U) {  // essentially only border words
                unsigned cU3 = M[sr - 3][w1 + 1], lU3 = M[sr - 3][w1], rU3 = M[sr - 3][w1 + 2];
                unsigned cD3 = M[sr + 3][w1 + 1], lD3 = M[sr + 3][w1], rD3 = M[sr + 3][w1 + 2];
                // s=9: (0,+-3), (+-3,0)
                unsigned h9 = (((W ^ __funnelshift_l(l0, W, 3)) & mlo3)
                             | ((W ^ __funnelshift_r(W, r0, 3)) & mhi3)
                             | ((W ^ cU3) & rvU3) | ((W ^ cD3) & rvD3)) & U;
                p0 |= h9; p3 |= h9; U &= ~h9;
                // s=10: (+-1,+-3), (+-3,+-1)
                unsigned h10 = (((((W ^ __funnelshift_l(lU1, cU1, 3)) & mlo3)
                                | ((W ^ __funnelshift_r(cU1, rU1, 3)) & mhi3)) & rvU1)
                              | ((((W ^ __funnelshift_l(lD1, cD1, 3)) & mlo3)
                                | ((W ^ __funnelshift_r(cD1, rD1, 3)) & mhi3)) & rvD1)
                              | ((((W ^ __funnelshift_l(lU3, cU3, 1)) & mlo1)
                                | ((W ^ __funnelshift_r(cU3, rU3, 1)) & mhi1)) & rvU3)
                              | ((((W ^ __funnelshift_l(lD3, cD3, 1)) & mlo1)
                                | ((W ^ __funnelshift_r(cD3, rD3, 1)) & mhi1)) & rvD3)) & U;
                p1 |= h10; p3 |= h10; U &= ~h10;
                // s=13: (+-2,+-3), (+-3,+-2)
                unsigned h13 = (((((W ^ __funnelshift_l(lU2, cU2, 3)) & mlo3)
                                | ((W ^ __funnelshift_r(cU2, rU2, 3)) & mhi3)) & rvU2)
                              | ((((W ^ __funnelshift_l(lD2, cD2, 3)) & mlo3)
                                | ((W ^ __funnelshift_r(cD2, rD2, 3)) & mhi3)) & rvD2)
                              | ((((W ^ __funnelshift_l(lU3, cU3, 2)) & mlo2)
                                | ((W ^ __funnelshift_r(cU3, rU3, 2)) & mhi2)) & rvU3)
                              | ((((W ^ __funnelshift_l(lD3, cD3, 2)) & mlo2)
                                | ((W ^ __funnelshift_r(cD3, rD3, 2)) & mhi2)) & rvD3)) & U;
                p0 |= h13; p2 |= h13; p3 |= h13;
                // unresolved keeps all-planes-0 -> exact fallback
            }
        }
        SP[f1][rr][w1] = make_uint4(p0, p1, p2, p3);
    }
    __syncthreads();

    // ---------------- Phase 2: warp = (row, half), lane = pixel ----------------
    int row  = warp >> 1;           // 0..3
    int half = warp & 1;            // word group
    int i2   = band * BAND + row;
    float acc = 0.0f;
    unsigned fb = 0u;               // fallback events: bit = wq*2 + side
#pragma unroll
    for (int wq = 0; wq < 4; ++wq) {
        int ww = half * 4 + wq;
        float w = w_sh[row][ww * 32 + lane];
        uint4 P = SP[0][row][ww];
        uint4 Q = SP[1][row][ww];
        int sp = (int)((P.x >> lane) & 1u) | ((int)((P.y >> lane) & 1u) << 1)
               | ((int)((P.z >> lane) & 1u) << 2) | ((int)((P.w >> lane) & 1u) << 3);
        int st = (int)((Q.x >> lane) & 1u) | ((int)((Q.y >> lane) & 1u) << 1)
               | ((int)((Q.z >> lane) & 1u) << 2) | ((int)((Q.w >> lane) & 1u) << 3);
        fb |= (sp == 0 ? 1u : 0u) << (wq * 2);
        fb |= (st == 0 ? 2u : 0u) << (wq * 2);
        acc += w * (float)(sp + st);
    }
    // exact fallback (prob ~1e-4 of ANY event in this input)
    while (fb) {
        int e = __ffs(fb) - 1; fb &= fb - 1;
        int side = e & 1, wq = e >> 1;
        int col = (half * 4 + wq) * 32 + lane;
        const float* ib = side ? tbase : pbase;
        bool cls = ib[(size_t)i2 * WW + col] > 0.5f;
        acc += w_sh[row][col] * slow_scan(ib, i2, col, cls);
    }

    // reduce: warp -> block
#pragma unroll
    for (int o = 16; o > 0; o >>= 1) acc += __shfl_xor_sync(0xFFFFFFFFu, acc, o);
    if (lane == 0) sred[warp] = acc;
    __syncthreads();

    // block partial -> global accumulator; last block finalizes + resets
    if (tid == 0) {
        float sum = 0.0f;
#pragma unroll
        for (int k = 0; k < 8; ++k) sum += sred[k];
        atomicAdd(&g_accum, sum);
        __threadfence();
        unsigned prev = atomicAdd(&g_done, 1u);
        if (prev == NBLK - 1) {
            float tot = *(volatile float*)&g_accum;
            *out = tot * (1.0f / (float)NPIX);
            *(volatile float*)&g_accum = 0.0f;      // reset for next graph replay
            *(volatile unsigned*)&g_done = 0u;
            __threadfence();
        }
    }
}

extern "C" void kernel_launch(void* const* d_in, const int* in_sizes, int n_in,
                              void* d_out, int out_size) {
    const float* pred   = (const float*)d_in[0];
    const float* target = (const float*)d_in[1];
    float* out = (float*)d_out;

    hd_loss_kernel<<<dim3(64, 8), 256>>>(pred, target, out);
}

// round 13
// speedup vs baseline: 1.2294x; 1.0896x over previous
#include <cuda_runtime.h>

#define HH 256
#define WW 256
#define NW 8                 // 256 cols / 32
#define NPIX (8 * HH * WW)   // mean denominator
#define NBLK 256             // 32 band-pairs x 8 batch
#define BAND 4               // core rows per band
#define WROWS 10             // window rows = BAND + 2*3

__device__ float    g_accum = 0.0f;
__device__ unsigned g_done  = 0u;

// ---------------------------------------------------------------------------
// Exact fallback: expanding float-based scan for nearest opposite-class pixel.
// Reached only when no opposite pixel lies within r^2 <= 13 (prob ~1e-4 of
// ANY event in this input). Exact for all inputs; 1e20 if none exists.
// ---------------------------------------------------------------------------
__device__ __noinline__ float slow_scan(const float* __restrict__ im, int i, int j, bool cls) {
    float best = 1e20f;
    for (int dd = 0; dd < HH; ++dd) {
        float dd2 = (float)(dd * dd);
        if (dd2 >= best) break;
#pragma unroll 1
        for (int s2 = 0; s2 < 2; ++s2) {
            if (s2 && dd == 0) continue;
            int r = s2 ? i - dd : i + dd;
            if (r < 0 || r >= HH) continue;
            const float* row = im + (size_t)r * WW;
            for (int dj = 0; dj < WW; ++dj) {
                float tot = dd2 + (float)(dj * dj);
                if (tot >= best) break;
                int c1 = j + dj, c2 = j - dj;
                if (c1 < WW && ((row[c1] > 0.5f) != cls)) { best = tot; break; }
                if (dj && c2 >= 0 && ((row[c2] > 0.5f) != cls)) { best = tot; break; }
            }
        }
    }
    return best;
}

// ---------------------------------------------------------------------------
// Word-task plane computation (R8 core). M = mask rows (10x10 incl. pads).
// Levels r^2 in {1,2,4,5,8} + gated {9,10,13}; s = p0+2p1+4p2+8p3.
// ---------------------------------------------------------------------------
__device__ __forceinline__ uint4 compute_planes(const unsigned (*M)[10], int i1, int sr, int w1) {
    unsigned W   = M[sr][w1 + 1];
    unsigned l0  = M[sr][w1],         r0  = M[sr][w1 + 2];
    unsigned cU1 = M[sr - 1][w1 + 1], lU1 = M[sr - 1][w1], rU1 = M[sr - 1][w1 + 2];
    unsigned cD1 = M[sr + 1][w1 + 1], lD1 = M[sr + 1][w1], rD1 = M[sr + 1][w1 + 2];

    unsigned mlo1 = (w1 == 0) ? 0xFFFFFFFEu : 0xFFFFFFFFu;
    unsigned mlo2 = (w1 == 0) ? 0xFFFFFFFCu : 0xFFFFFFFFu;
    unsigned mlo3 = (w1 == 0) ? 0xFFFFFFF8u : 0xFFFFFFFFu;
    unsigned mhi1 = (w1 == 7) ? 0x7FFFFFFFu : 0xFFFFFFFFu;
    unsigned mhi2 = (w1 == 7) ? 0x3FFFFFFFu : 0xFFFFFFFFu;
    unsigned mhi3 = (w1 == 7) ? 0x1FFFFFFFu : 0xFFFFFFFFu;
    unsigned rvU1 = (i1 >= 1)      ? 0xFFFFFFFFu : 0u;
    unsigned rvD1 = (i1 <= HH - 2) ? 0xFFFFFFFFu : 0u;
    unsigned rvU2 = (i1 >= 2)      ? 0xFFFFFFFFu : 0u;
    unsigned rvD2 = (i1 <= HH - 3) ? 0xFFFFFFFFu : 0u;
    unsigned rvU3 = (i1 >= 3)      ? 0xFFFFFFFFu : 0u;
    unsigned rvD3 = (i1 <= HH - 4) ? 0xFFFFFFFFu : 0u;

    // s=1: (0,+-1), (+-1,0)
    unsigned h1 = ((W ^ __funnelshift_l(l0, W, 1)) & mlo1)
                | ((W ^ __funnelshift_r(W, r0, 1)) & mhi1)
                | ((W ^ cU1) & rvU1) | ((W ^ cD1) & rvD1);
    // s=2: (+-1,+-1)
    unsigned h2 = (((((W ^ __funnelshift_l(lU1, cU1, 1)) & mlo1)
                   | ((W ^ __funnelshift_r(cU1, rU1, 1)) & mhi1)) & rvU1)
                 | ((((W ^ __funnelshift_l(lD1, cD1, 1)) & mlo1)
                   | ((W ^ __funnelshift_r(cD1, rD1, 1)) & mhi1)) & rvD1)) & ~h1;
    unsigned p0 = h1, p1 = h2, p2 = 0u, p3 = 0u;
    unsigned U = ~(h1 | h2);
    if (U) {
        unsigned cU2 = M[sr - 2][w1 + 1], lU2 = M[sr - 2][w1], rU2 = M[sr - 2][w1 + 2];
        unsigned cD2 = M[sr + 2][w1 + 1], lD2 = M[sr + 2][w1], rD2 = M[sr + 2][w1 + 2];
        // s=4: (0,+-2), (+-2,0)
        unsigned h4 = (((W ^ __funnelshift_l(l0, W, 2)) & mlo2)
                     | ((W ^ __funnelshift_r(W, r0, 2)) & mhi2)
                     | ((W ^ cU2) & rvU2) | ((W ^ cD2) & rvD2)) & U;
        p2 = h4; U &= ~h4;
        // s=5: (+-1,+-2), (+-2,+-1)
        unsigned h5 = (((((W ^ __funnelshift_l(lU1, cU1, 2)) & mlo2)
                       | ((W ^ __funnelshift_r(cU1, rU1, 2)) & mhi2)) & rvU1)
                     | ((((W ^ __funnelshift_l(lD1, cD1, 2)) & mlo2)
                       | ((W ^ __funnelshift_r(cD1, rD1, 2)) & mhi2)) & rvD1)
                     | ((((W ^ __funnelshift_l(lU2, cU2, 1)) & mlo1)
                       | ((W ^ __funnelshift_r(cU2, rU2, 1)) & mhi1)) & rvU2)
                     | ((((W ^ __funnelshift_l(lD2, cD2, 1)) & mlo1)
                       | ((W ^ __funnelshift_r(cD2, rD2, 1)) & mhi1)) & rvD2)) & U;
        p0 |= h5; p2 |= h5; U &= ~h5;
        // s=8: (+-2,+-2)
        unsigned h8 = (((((W ^ __funnelshift_l(lU2, cU2, 2)) & mlo2)
                       | ((W ^ __funnelshift_r(cU2, rU2, 2)) & mhi2)) & rvU2)
                     | ((((W ^ __funnelshift_l(lD2, cD2, 2)) & mlo2)
                       | ((W ^ __funnelshift_r(cD2, rD2, 2)) & mhi2)) & rvD2)) & U;
        p3 = h8; U &= ~h8;
        if (U) {  // essentially only border words
            unsigned cU3 = M[sr - 3][w1 + 1], lU3 = M[sr - 3][w1], rU3 = M[sr - 3][w1 + 2];
            unsigned cD3 = M[sr + 3][w1 + 1], lD3 = M[sr + 3][w1], rD3 = M[sr + 3][w1 + 2];
            // s=9: (0,+-3), (+-3,0)
            unsigned h9 = (((W ^ __funnelshift_l(l0, W, 3)) & mlo3)
                         | ((W ^ __funnelshift_r(W, r0, 3)) & mhi3)
                         | ((W ^ cU3) & rvU3) | ((W ^ cD3) & rvD3)) & U;
            p0 |= h9; p3 |= h9; U &= ~h9;
            // s=10: (+-1,+-3), (+-3,+-1)
            unsigned h10 = (((((W ^ __funnelshift_l(lU1, cU1, 3)) & mlo3)
                            | ((W ^ __funnelshift_r(cU1, rU1, 3)) & mhi3)) & rvU1)
                          | ((((W ^ __funnelshift_l(lD1, cD1, 3)) & mlo3)
                            | ((W ^ __funnelshift_r(cD1, rD1, 3)) & mhi3)) & rvD1)
                          | ((((W ^ __funnelshift_l(lU3, cU3, 1)) & mlo1)
                            | ((W ^ __funnelshift_r(cU3, rU3, 1)) & mhi1)) & rvU3)
                          | ((((W ^ __funnelshift_l(lD3, cD3, 1)) & mlo1)
                            | ((W ^ __funnelshift_r(cD3, rD3, 1)) & mhi1)) & rvD3)) & U;
            p1 |= h10; p3 |= h10; U &= ~h10;
            // s=13: (+-2,+-3), (+-3,+-2)
            unsigned h13 = (((((W ^ __funnelshift_l(lU2, cU2, 3)) & mlo3)
                            | ((W ^ __funnelshift_r(cU2, rU2, 3)) & mhi3)) & rvU2)
                          | ((((W ^ __funnelshift_l(lD2, cD2, 3)) & mlo3)
                            | ((W ^ __funnelshift_r(cD2, rD2, 3)) & mhi3)) & rvD2)
                          | ((((W ^ __funnelshift_l(lU3, cU3, 2)) & mlo2)
                            | ((W ^ __funnelshift_r(cU3, rU3, 2)) & mhi2)) & rvU3)
                          | ((((W ^ __funnelshift_l(lD3, cD3, 2)) & mlo2)
                            | ((W ^ __funnelshift_r(cD3, rD3, 2)) & mhi2)) & rvD3)) & U;
            p0 |= h13; p2 |= h13; p3 |= h13;
            // unresolved keeps all-planes-0 -> exact fallback
        }
    }
    return make_uint4(p0, p1, p2, p3);
}

// ---------------------------------------------------------------------------
// Two-band software-pipelined kernel. Block = (band pair, batch), 256 thr.
// ---------------------------------------------------------------------------
__global__ void __launch_bounds__(256) hd_loss_kernel(const float* __restrict__ pred,
                                                      const float* __restrict__ target,
                                                      float* __restrict__ out) {
    int bpair = blockIdx.x;         // 0..31
    int b     = blockIdx.y;         // 0..7
    int tid   = threadIdx.x;
    int lane  = tid & 31;
    int warp  = tid >> 5;           // 0..7

    __shared__ unsigned SM[2][2][WROWS][10];   // [band q][img][row][word+pads]
    __shared__ uint4    SP[2][2][BAND][NW];    // [band q][img][row][word]
    __shared__ float    w_sh[2][BAND][WW];     // [band q][row][col]
    __shared__ float    sred[8];

    const float* pbase = pred   + (size_t)b * HH * WW;
    const float* tbase = target + (size_t)b * HH * WW;
    const int bq0 = bpair * 2, bq1 = bpair * 2 + 1;

    // zero pads: 2q x 2img x 10 rows x 2 cols = 80 slots
    if (tid < 80) {
        int q = tid / 40, rem = tid % 40;
        int f = rem / 20, rem2 = rem % 20;
        SM[q][f][rem2 >> 1][(rem2 & 1) * 9] = 0u;
    }

    // ---- phase0(band 0): warp = word column, k = window row ----
#pragma unroll
    for (int k = 0; k < WROWS; ++k) {
        int gi = bq0 * BAND - 3 + k;
        gi = gi < 0 ? 0 : (gi > HH - 1 ? HH - 1 : gi);
        float vp = pbase[(size_t)gi * WW + warp * 32 + lane];
        float vt = tbase[(size_t)gi * WW + warp * 32 + lane];
        unsigned mp = __ballot_sync(0xFFFFFFFFu, vp > 0.5f);
        unsigned mt = __ballot_sync(0xFFFFFFFFu, vt > 0.5f);
        if (lane == 0) { SM[0][0][k][warp + 1] = mp; SM[0][1][k][warp + 1] = mt; }
        if (k >= 3 && k < 3 + BAND) {
            float d = vp - vt;
            w_sh[0][k - 3][warp * 32 + lane] = d * d;
        }
    }
    __syncthreads();

    // ---- overlap region 1: phase1(0) on warps 0-1 || band-1 loads on warps 2-7 ----
    if (warp < 2) {
        // issue band-1 loads first (latency overlapped with phase1 below)
        float vp1[WROWS], vt1[WROWS];
#pragma unroll
        for (int k = 0; k < WROWS; ++k) {
            int gi = bq1 * BAND - 3 + k;
            gi = gi < 0 ? 0 : (gi > HH - 1 ? HH - 1 : gi);
            vp1[k] = pbase[(size_t)gi * WW + warp * 32 + lane];
            vt1[k] = tbase[(size_t)gi * WW + warp * 32 + lane];
        }
        // phase1(0): 64 tasks = all lanes of warps 0-1
        {
            int f1 = tid >> 5, rr = (tid >> 3) & 3, w1 = tid & 7;
            SP[0][f1][rr][w1] = compute_planes(SM[0][f1], bq0 * BAND + rr, rr + 3, w1);
        }
        // band-1 ballots + stores (loads have landed by now)
#pragma unroll
        for (int k = 0; k < WROWS; ++k) {
            unsigned mp = __ballot_sync(0xFFFFFFFFu, vp1[k] > 0.5f);
            unsigned mt = __ballot_sync(0xFFFFFFFFu, vt1[k] > 0.5f);
            if (lane == 0) { SM[1][0][k][warp + 1] = mp; SM[1][1][k][warp + 1] = mt; }
            if (k >= 3 && k < 3 + BAND) {
                float d = vp1[k] - vt1[k];
                w_sh[1][k - 3][warp * 32 + lane] = d * d;
            }
        }
    } else {
        // warps 2-7: plain band-1 load+ballot+store (LDG stall hidden by warps 0-1 issue)
#pragma unroll
        for (int k = 0; k < WROWS; ++k) {
            int gi = bq1 * BAND - 3 + k;
            gi = gi < 0 ? 0 : (gi > HH - 1 ? HH - 1 : gi);
            float vp = pbase[(size_t)gi * WW + warp * 32 + lane];
            float vt = tbase[(size_t)gi * WW + warp * 32 + lane];
            unsigned mp = __ballot_sync(0xFFFFFFFFu, vp > 0.5f);
            unsigned mt = __ballot_sync(0xFFFFFFFFu, vt > 0.5f);
            if (lane == 0) { SM[1][0][k][warp + 1] = mp; SM[1][1][k][warp + 1] = mt; }
            if (k >= 3 && k < 3 + BAND) {
                float d = vp - vt;
                w_sh[1][k - 3][warp * 32 + lane] = d * d;
            }
        }
    }
    __syncthreads();

    // ---- overlap region 2: phase1(1) on warps 0-1, then phase2(0) for all ----
    if (warp < 2) {
        int f1 = tid >> 5, rr = (tid >> 3) & 3, w1 = tid & 7;
        SP[1][f1][rr][w1] = compute_planes(SM[1][f1], bq1 * BAND + rr, rr + 3, w1);
    }

    float acc = 0.0f;
    int row  = warp >> 1;
    int half = warp & 1;

#pragma unroll
    for (int q = 0; q < 2; ++q) {
        if (q == 1) __syncthreads();          // SP[1] ready before band-1 decode
        int i2 = (bpair * 2 + q) * BAND + row;
        unsigned fb = 0u;
#pragma unroll
        for (int wq = 0; wq < 4; ++wq) {
            int ww = half * 4 + wq;
            float w = w_sh[q][row][ww * 32 + lane];
            uint4 P = SP[q][0][row][ww];
            uint4 Q = SP[q][1][row][ww];
            int sp = (int)((P.x >> lane) & 1u) | ((int)((P.y >> lane) & 1u) << 1)
                   | ((int)((P.z >> lane) & 1u) << 2) | ((int)((P.w >> lane) & 1u) << 3);
            int st = (int)((Q.x >> lane) & 1u) | ((int)((Q.y >> lane) & 1u) << 1)
                   | ((int)((Q.z >> lane) & 1u) << 2) | ((int)((Q.w >> lane) & 1u) << 3);
            fb |= (sp == 0 ? 1u : 0u) << (wq * 2);
            fb |= (st == 0 ? 2u : 0u) << (wq * 2);
            acc += w * (float)(sp + st);
        }
        // exact fallback (prob ~1e-4 of ANY event in this input)
        while (fb) {
            int e = __ffs(fb) - 1; fb &= fb - 1;
            int side = e & 1, wq = e >> 1;
            int col = (half * 4 + wq) * 32 + lane;
            const float* ib = side ? tbase : pbase;
            bool cls = ib[(size_t)i2 * WW + col] > 0.5f;
            acc += w_sh[q][row][col] * slow_scan(ib, i2, col, cls);
        }
    }

    // ---- reduce: warp -> block -> global ----
#pragma unroll
    for (int o = 16; o > 0; o >>= 1) acc += __shfl_xor_sync(0xFFFFFFFFu, acc, o);
    if (lane == 0) sred[warp] = acc;
    __syncthreads();

    if (tid == 0) {
        float sum = 0.0f;
#pragma unroll
        for (int k = 0; k < 8; ++k) sum += sred[k];
        atomicAdd(&g_accum, sum);
        __threadfence();
        unsigned prev = atomicAdd(&g_done, 1u);
        if (prev == NBLK - 1) {
            float tot = *(volatile float*)&g_accum;
            *out = tot * (1.0f / (float)NPIX);
            *(volatile float*)&g_accum = 0.0f;      // reset for next graph replay
            *(volatile unsigned*)&g_done = 0u;
            __threadfence();
        }
    }
}

extern "C" void kernel_launch(void* const* d_in, const int* in_sizes, int n_in,
                              void* d_out, int out_size) {
    const float* pred   = (const float*)d_in[0];
    const float* target = (const float*)d_in[1];
    float* out = (float*)d_out;

    hd_loss_kernel<<<dim3(32, 8), 256>>>(pred, target, out);
}

// round 14
// speedup vs baseline: 1.2610x; 1.0257x over previous
#include <cuda_runtime.h>

#define HH 256
#define WW 256
#define NW 8                 // 256 cols / 32
#define NPIX (8 * HH * WW)   // mean denominator
#define NBLK 512             // 64 bands x 8 batch
#define BAND 4               // core rows per block
#define WROWS 10             // window rows = BAND + 2*3

__device__ float    g_accum = 0.0f;
__device__ unsigned g_done  = 0u;

// ---------------------------------------------------------------------------
// Exact fallback: expanding float-based scan for nearest opposite-class pixel.
// Reached only when no opposite pixel lies within r^2 <= 13 (prob ~1e-4 of
// ANY event in this input). Exact for all inputs; 1e20 if none exists.
// ---------------------------------------------------------------------------
__device__ __noinline__ float slow_scan(const float* __restrict__ im, int i, int j, bool cls) {
    float best = 1e20f;
    for (int dd = 0; dd < HH; ++dd) {
        float dd2 = (float)(dd * dd);
        if (dd2 >= best) break;
#pragma unroll 1
        for (int s2 = 0; s2 < 2; ++s2) {
            if (s2 && dd == 0) continue;
            int r = s2 ? i - dd : i + dd;
            if (r < 0 || r >= HH) continue;
            const float* row = im + (size_t)r * WW;
            for (int dj = 0; dj < WW; ++dj) {
                float tot = dd2 + (float)(dj * dj);
                if (tot >= best) break;
                int c1 = j + dj, c2 = j - dj;
                if (c1 < WW && ((row[c1] > 0.5f) != cls)) { best = tot; break; }
                if (dj && c2 >= 0 && ((row[c2] > 0.5f) != cls)) { best = tot; break; }
            }
        }
    }
    return best;
}

// ---------------------------------------------------------------------------
// Single fused kernel (R8 structure; w kept in registers via aligned warp
// mapping). Block = (band of 4 rows, batch), 256 threads (8 warps).
// Phase 0: warp = word column; k = window row; ballots build masks; core-row
//          w = (p-t)^2 stays in registers (same warp uses it in phase 2).
// Phase 1: threads 0..63 = (image, row, word) -> 4 bit-planes, gated levels
//          r^2 in {1,2,4,5,8} + {9,10,13}. s = p0+2p1+4p2+8p3.
// Phase 2: warp = word column, iterate 4 core rows: acc += w[row]*(sp+st);
//          s==0 -> exact slow_scan.
// Output: last-block finalize (idempotent across graph replays).
// ---------------------------------------------------------------------------
__global__ void __launch_bounds__(256) hd_loss_kernel(const float* __restrict__ pred,
                                                      const float* __restrict__ target,
                                                      float* __restrict__ out) {
    int band = blockIdx.x;          // 0..63
    int b    = blockIdx.y;          // 0..7
    int tid  = threadIdx.x;         // 0..255
    int lane = tid & 31;
    int warp = tid >> 5;            // 0..7 == word column

    __shared__ unsigned SM[2][WROWS][10];   // window rows band*4-3..+6, pad cols 0,9
    __shared__ uint4    SP[2][BAND][NW];    // bit-planes p0..p3
    __shared__ float    sred[8];

    const float* pbase = pred   + (size_t)b * HH * WW;
    const float* tbase = target + (size_t)b * HH * WW;

    // zero pads: 2 img x 10 rows x 2 pad cols = 40 slots
    if (tid < 40) {
        int f = tid / 20, rr = (tid >> 1) % 10, cc = tid & 1;
        SM[f][rr][cc * 9] = 0u;
    }

    // ---------------- Phase 0: warp = word column; w stays in registers ----------------
    float w[BAND];
    {
        int col = warp * 32 + lane;
#pragma unroll
        for (int k = 0; k < WROWS; ++k) {
            int gi = band * BAND - 3 + k;
            gi = gi < 0 ? 0 : (gi > HH - 1 ? HH - 1 : gi);   // clamp; rv masks fix validity
            float vp = pbase[(size_t)gi * WW + col];
            float vt = tbase[(size_t)gi * WW + col];
            unsigned mp = __ballot_sync(0xFFFFFFFFu, vp > 0.5f);
            unsigned mt = __ballot_sync(0xFFFFFFFFu, vt > 0.5f);
            if (lane == 0) {
                SM[0][k][warp + 1] = mp;
                SM[1][k][warp + 1] = mt;
            }
            if (k >= 3 && k < 3 + BAND) {
                float d = vp - vt;
                w[k - 3] = d * d;
            }
        }
    }
    __syncthreads();

    // ---------------- Phase 1: one word-task per thread (64 tasks) ----------------
    if (tid < 64) {
        int f1 = tid >> 5;          // 0 = pred, 1 = target
        int rr = (tid >> 3) & 3;    // core row in band
        int w1 = tid & 7;           // word
        int i1 = band * BAND + rr;
        int sr = rr + 3;
        const unsigned (*M)[10] = SM[f1];

        unsigned W   = M[sr][w1 + 1];
        unsigned l0  = M[sr][w1],         r0  = M[sr][w1 + 2];
        unsigned cU1 = M[sr - 1][w1 + 1], lU1 = M[sr - 1][w1], rU1 = M[sr - 1][w1 + 2];
        unsigned cD1 = M[sr + 1][w1 + 1], lD1 = M[sr + 1][w1], rD1 = M[sr + 1][w1 + 2];

        unsigned mlo1 = (w1 == 0) ? 0xFFFFFFFEu : 0xFFFFFFFFu;
        unsigned mlo2 = (w1 == 0) ? 0xFFFFFFFCu : 0xFFFFFFFFu;
        unsigned mlo3 = (w1 == 0) ? 0xFFFFFFF8u : 0xFFFFFFFFu;
        unsigned mhi1 = (w1 == 7) ? 0x7FFFFFFFu : 0xFFFFFFFFu;
        unsigned mhi2 = (w1 == 7) ? 0x3FFFFFFFu : 0xFFFFFFFFu;
        unsigned mhi3 = (w1 == 7) ? 0x1FFFFFFFu : 0xFFFFFFFFu;
        unsigned rvU1 = (i1 >= 1)      ? 0xFFFFFFFFu : 0u;
        unsigned rvD1 = (i1 <= HH - 2) ? 0xFFFFFFFFu : 0u;
        unsigned rvU2 = (i1 >= 2)      ? 0xFFFFFFFFu : 0u;
        unsigned rvD2 = (i1 <= HH - 3) ? 0xFFFFFFFFu : 0u;
        unsigned rvU3 = (i1 >= 3)      ? 0xFFFFFFFFu : 0u;
        unsigned rvD3 = (i1 <= HH - 4) ? 0xFFFFFFFFu : 0u;

        // s=1: (0,+-1), (+-1,0)
        unsigned h1 = ((W ^ __funnelshift_l(l0, W, 1)) & mlo1)
                    | ((W ^ __funnelshift_r(W, r0, 1)) & mhi1)
                    | ((W ^ cU1) & rvU1) | ((W ^ cD1) & rvD1);
        // s=2: (+-1,+-1)
        unsigned h2 = (((((W ^ __funnelshift_l(lU1, cU1, 1)) & mlo1)
                       | ((W ^ __funnelshift_r(cU1, rU1, 1)) & mhi1)) & rvU1)
                     | ((((W ^ __funnelshift_l(lD1, cD1, 1)) & mlo1)
                       | ((W ^ __funnelshift_r(cD1, rD1, 1)) & mhi1)) & rvD1)) & ~h1;
        unsigned p0 = h1, p1 = h2, p2 = 0u, p3 = 0u;
        unsigned U = ~(h1 | h2);
        if (U) {
            unsigned cU2 = M[sr - 2][w1 + 1], lU2 = M[sr - 2][w1], rU2 = M[sr - 2][w1 + 2];
            unsigned cD2 = M[sr + 2][w1 + 1], lD2 = M[sr + 2][w1], rD2 = M[sr + 2][w1 + 2];
            // s=4: (0,+-2), (+-2,0)
            unsigned h4 = (((W ^ __funnelshift_l(l0, W, 2)) & mlo2)
                         | ((W ^ __funnelshift_r(W, r0, 2)) & mhi2)
                         | ((W ^ cU2) & rvU2) | ((W ^ cD2) & rvD2)) & U;
            p2 = h4; U &= ~h4;
            // s=5: (+-1,+-2), (+-2,+-1)
            unsigned h5 = (((((W ^ __funnelshift_l(lU1, cU1, 2)) & mlo2)
                           | ((W ^ __funnelshift_r(cU1, rU1, 2)) & mhi2)) & rvU1)
                         | ((((W ^ __funnelshift_l(lD1, cD1, 2)) & mlo2)
                           | ((W ^ __funnelshift_r(cD1, rD1, 2)) & mhi2)) & rvD1)
                         | ((((W ^ __funnelshift_l(lU2, cU2, 1)) & mlo1)
                           | ((W ^ __funnelshift_r(cU2, rU2, 1)) & mhi1)) & rvU2)
                         | ((((W ^ __funnelshift_l(lD2, cD2, 1)) & mlo1)
                           | ((W ^ __funnelshift_r(cD2, rD2, 1)) & mhi1)) & rvD2)) & U;
            p0 |= h5; p2 |= h5; U &= ~h5;
            // s=8: (+-2,+-2)
            unsigned h8 = (((((W ^ __funnelshift_l(lU2, cU2, 2)) & mlo2)
                           | ((W ^ __funnelshift_r(cU2, rU2, 2)) & mhi2)) & rvU2)
                         | ((((W ^ __funnelshift_l(lD2, cD2, 2)) & mlo2)
                           | ((W ^ __funnelshift_r(cD2, rD2, 2)) & mhi2)) & rvD2)) & U;
            p3 = h8; U &= ~h8;
            if (U) {  // essentially only border words
                unsigned cU3 = M[sr - 3][w1 + 1], lU3 = M[sr - 3][w1], rU3 = M[sr - 3][w1 + 2];
                unsigned cD3 = M[sr + 3][w1 + 1], lD3 = M[sr + 3][w1], rD3 = M[sr + 3][w1 + 2];
                // s=9: (0,+-3), (+-3,0)
                unsigned h9 = (((W ^ __funnelshift_l(l0, W, 3)) & mlo3)
                             | ((W ^ __funnelshift_r(W, r0, 3)) & mhi3)
                             | ((W ^ cU3) & rvU3) | ((W ^ cD3) & rvD3)) & U;
                p0 |= h9; p3 |= h9; U &= ~h9;
                // s=10: (+-1,+-3), (+-3,+-1)
                unsigned h10 = (((((W ^ __funnelshift_l(lU1, cU1, 3)) & mlo3)
                                | ((W ^ __funnelshift_r(cU1, rU1, 3)) & mhi3)) & rvU1)
                              | ((((W ^ __funnelshift_l(lD1, cD1, 3)) & mlo3)
                                | ((W ^ __funnelshift_r(cD1, rD1, 3)) & mhi3)) & rvD1)
                              | ((((W ^ __funnelshift_l(lU3, cU3, 1)) & mlo1)
                                | ((W ^ __funnelshift_r(cU3, rU3, 1)) & mhi1)) & rvU3)
                              | ((((W ^ __funnelshift_l(lD3, cD3, 1)) & mlo1)
                                | ((W ^ __funnelshift_r(cD3, rD3, 1)) & mhi1)) & rvD3)) & U;
                p1 |= h10; p3 |= h10; U &= ~h10;
                // s=13: (+-2,+-3), (+-3,+-2)
                unsigned h13 = (((((W ^ __funnelshift_l(lU2, cU2, 3)) & mlo3)
                                | ((W ^ __funnelshift_r(cU2, rU2, 3)) & mhi3)) & rvU2)
                              | ((((W ^ __funnelshift_l(lD2, cD2, 3)) & mlo3)
                                | ((W ^ __funnelshift_r(cD2, rD2, 3)) & mhi3)) & rvD2)
                              | ((((W ^ __funnelshift_l(lU3, cU3, 2)) & mlo2)
                                | ((W ^ __funnelshift_r(cU3, rU3, 2)) & mhi2)) & rvU3)
                              | ((((W ^ __funnelshift_l(lD3, cD3, 2)) & mlo2)
                                | ((W ^ __funnelshift_r(cD3, rD3, 2)) & mhi2)) & rvD3)) & U;
                p0 |= h13; p2 |= h13; p3 |= h13;
                // unresolved keeps all-planes-0 -> exact fallback
            }
        }
        SP[f1][rr][w1] = make_uint4(p0, p1, p2, p3);
    }
    __syncthreads();

    // ---------------- Phase 2: warp = word column, iterate 4 core rows ----------------
    float acc = 0.0f;
    unsigned fb = 0u;               // fallback events: bit = row*2 + side
#pragma unroll
    for (int row = 0; row < BAND; ++row) {
        uint4 P = SP[0][row][warp];
        uint4 Q = SP[1][row][warp];
        int sp = (int)((P.x >> lane) & 1u) | ((int)((P.y >> lane) & 1u) << 1)
               | ((int)((P.z >> lane) & 1u) << 2) | ((int)((P.w >> lane) & 1u) << 3);
        int st = (int)((Q.x >> lane) & 1u) | ((int)((Q.y >> lane) & 1u) << 1)
               | ((int)((Q.z >> lane) & 1u) << 2) | ((int)((Q.w >> lane) & 1u) << 3);
        fb |= (sp == 0 ? 1u : 0u) << (row * 2);
        fb |= (st == 0 ? 2u : 0u) << (row * 2);
        acc += w[row] * (float)(sp + st);
    }
    // exact fallback (prob ~1e-4 of ANY event in this input)
    while (fb) {
        int e = __ffs(fb) - 1; fb &= fb - 1;
        int side = e & 1, row = e >> 1;
        int i2  = band * BAND + row;
        int col = warp * 32 + lane;
        const float* ib = side ? tbase : pbase;
        bool cls = ib[(size_t)i2 * WW + col] > 0.5f;
        acc += w[row] * slow_scan(ib, i2, col, cls);
    }

    // reduce: warp -> block
#pragma unroll
    for (int o = 16; o > 0; o >>= 1) acc += __shfl_xor_sync(0xFFFFFFFFu, acc, o);
    if (lane == 0) sred[warp] = acc;
    __syncthreads();

    // block partial -> global accumulator; last block finalizes + resets
    if (tid == 0) {
        float sum = 0.0f;
#pragma unroll
        for (int k = 0; k < 8; ++k) sum += sred[k];
        atomicAdd(&g_accum, sum);
        __threadfence();
        unsigned prev = atomicAdd(&g_done, 1u);
        if (prev == NBLK - 1) {
            float tot = *(volatile float*)&g_accum;
            *out = tot * (1.0f / (float)NPIX);
            *(volatile float*)&g_accum = 0.0f;      // reset for next graph replay
            *(volatile unsigned*)&g_done = 0u;
            __threadfence();
        }
    }
}

extern "C" void kernel_launch(void* const* d_in, const int* in_sizes, int n_in,
                              void* d_out, int out_size) {
    const float* pred   = (const float*)d_in[0];
    const float* target = (const float*)d_in[1];
    float* out = (float*)d_out;

    hd_loss_kernel<<<dim3(64, 8), 256>>>(pred, target, out);
}